// round 10
// baseline (speedup 1.0000x reference)
#include <cuda_runtime.h>
#include <cuda_fp16.h>
#include <cstdint>

// ----------------------------------------------------------------------------
// BitLinear: y = RMSNorm(x) @ w_q^T * gamma
// R1: harness PTX is baseline sm_103 (no 'a') -> no tcgen05.
// R8: occ2 + frag pipeline: tensor 82.6%. R9: 64x64 warp tiles, 128-thr CTAs,
//     occ2: tensor 89.5%, GEMM 508us, total 553us. Mainloop tensor-saturated
//     (2 warps x 128 HMMA x rt8 ~= kt wall); residual = prologue/epilogue/wave
//     transitions.
// R10: persistent CTAs (304 = 152 SMs x 2) with flat cross-tile pipeline:
//     cp.async stages + frag buffers never drain across tiles; epilogue
//     overlaps next tile's HMMAs.
// ----------------------------------------------------------------------------

#define DIN   4096
#define DOUT  4096
#define MROWS 8192

__device__ __align__(256) __half g_xn[(size_t)MROWS * DIN];
__device__ __align__(256) __half g_wq[(size_t)DOUT * DIN];

// ---------------------------- PTX helpers -----------------------------------
__device__ __forceinline__ uint32_t smem_u32(const void* p) {
    uint32_t a;
    asm("{ .reg .u64 t; cvta.to.shared.u64 t, %1; cvt.u32.u64 %0, t; }"
        : "=r"(a) : "l"(p));
    return a;
}

__device__ __forceinline__ void cp_async16(uint32_t dst, const void* src) {
    asm volatile("cp.async.cg.shared.global [%0], [%1], 16;"
                 :: "r"(dst), "l"(src));
}

#define CP_COMMIT() asm volatile("cp.async.commit_group;" ::: "memory")

#define LDSM_X4(r0, r1, r2, r3, addr) \
    asm volatile("ldmatrix.sync.aligned.m8n8.x4.shared.b16 {%0,%1,%2,%3}, [%4];" \
                 : "=r"(r0), "=r"(r1), "=r"(r2), "=r"(r3) : "r"(addr))

#define MMA16816(d, a, b0, b1) \
    asm volatile("mma.sync.aligned.m16n8k16.row.col.f32.f16.f16.f32 " \
                 "{%0,%1,%2,%3}, {%4,%5,%6,%7}, {%8,%9}, {%0,%1,%2,%3};" \
                 : "+f"((d)[0]), "+f"((d)[1]), "+f"((d)[2]), "+f"((d)[3]) \
                 : "r"((a)[0]), "r"((a)[1]), "r"((a)[2]), "r"((a)[3]), \
                   "r"(b0), "r"(b1))

// ----------------------------- GEMM config ----------------------------------
constexpr int BM = 128, BN = 128, BK = 64;
constexpr int KTILES = DIN / BK;               // 64
constexpr int STAGES = 3;
constexpr int TILE_B  = BM * BK * 2;           // 16384 B per fp16 tile
constexpr int STAGE_B = 2 * TILE_B;            // A + B = 32768
constexpr int SMEM_SZ = STAGES * STAGE_B;      // 98304 (2 CTAs/SM)
constexpr int NTHREADS = 128;                  // 4 warps, warp tile 64x64
constexpr int GRID = 304;                      // 152 SMs x 2 CTAs (persistent)
constexpr int NTILES = (MROWS / BM) * (DOUT / BN);  // 2048
constexpr int TILES_N = DOUT / BN;             // 32

// ------------------------ Kernel 0: dummy (ncu window shift) -----------------
__global__ void dummy_kernel() {}

// ------------------------ Kernel 1: RMSNorm -> fp16 --------------------------
__global__ __launch_bounds__(256) void rmsnorm_kernel(
    const float* __restrict__ x, const float* __restrict__ nw) {
    const int row = blockIdx.x;
    const float4* xr = reinterpret_cast<const float4*>(x) + (size_t)row * (DIN / 4);
    const float4* nw4 = reinterpret_cast<const float4*>(nw);
    const int t = threadIdx.x;

    float4 v[4];
    float ss = 0.f;
#pragma unroll
    for (int i = 0; i < 4; i++) {
        v[i] = xr[t + i * 256];
        ss += v[i].x * v[i].x + v[i].y * v[i].y + v[i].z * v[i].z + v[i].w * v[i].w;
    }
#pragma unroll
    for (int o = 16; o > 0; o >>= 1) ss += __shfl_xor_sync(0xffffffffu, ss, o);

    __shared__ float wss[8];
    __shared__ float s_scale;
    if ((t & 31) == 0) wss[t >> 5] = ss;
    __syncthreads();
    if (t == 0) {
        float tot = 0.f;
#pragma unroll
        for (int i = 0; i < 8; i++) tot += wss[i];
        s_scale = rsqrtf(tot * (1.0f / DIN) + 1e-6f);
    }
    __syncthreads();
    const float sc = s_scale;

    uint2* xo = reinterpret_cast<uint2*>(g_xn + (size_t)row * DIN);
#pragma unroll
    for (int i = 0; i < 4; i++) {
        float4 w = nw4[t + i * 256];
        __half2 h01 = __floats2half2_rn(v[i].x * sc * w.x, v[i].y * sc * w.y);
        __half2 h23 = __floats2half2_rn(v[i].z * sc * w.z, v[i].w * sc * w.w);
        uint2 u;
        u.x = *reinterpret_cast<uint32_t*>(&h01);
        u.y = *reinterpret_cast<uint32_t*>(&h23);
        xo[t + i * 256] = u;
    }
}

// ------------------------ Kernel 2: w_q fp32 -> fp16 --------------------------
__global__ __launch_bounds__(256) void wconv_kernel(const float* __restrict__ w) {
    const size_t gid = (size_t)blockIdx.x * 256 + threadIdx.x;
    const float4* w4 = reinterpret_cast<const float4*>(w);
    uint2* o = reinterpret_cast<uint2*>(g_wq);
#pragma unroll
    for (int i = 0; i < 4; i++) {
        size_t idx = gid + (size_t)i * 1048576;
        float4 v = w4[idx];
        __half2 h01 = __floats2half2_rn(v.x, v.y);
        __half2 h23 = __floats2half2_rn(v.z, v.w);
        uint2 u;
        u.x = *reinterpret_cast<uint32_t*>(&h01);
        u.y = *reinterpret_cast<uint32_t*>(&h23);
        o[idx] = u;
    }
}

// ------------------------ Kernel 3: persistent HMMA GEMM ---------------------
// 128 threads = 4 warps, 2(m) x 2(n), warp tile 64x64; 2 CTAs/SM; persistent.
__global__ __launch_bounds__(NTHREADS, 2)
void bitlinear_gemm_kernel(const float* __restrict__ gamma, float* __restrict__ out) {
    extern __shared__ char smem[];
    const uint32_t sb = smem_u32(smem);
    const int tid = threadIdx.x;
    const int wid = tid >> 5;
    const int lane = tid & 31;
    const int warp_m = wid >> 1;       // 0..1
    const int warp_n = wid & 1;        // 0..1
    const int bid = blockIdx.x;

    const int my_ntiles = (NTILES - bid + GRID - 1) / GRID;
    const int total = my_ntiles * KTILES;

    // ---- per-thread copy geometry: 1024 chunks/tile, 128 thr -> 8 each
    const int cc = tid & 7;
    const int r0c = tid >> 3;          // 0..15; r&7 invariant under +16
    const uint32_t so_base = (uint32_t)(r0c * 128 + ((cc ^ (r0c & 7)) << 4));

    // fill stage `slot` with flat-iteration `it`'s K-chunk
    auto fill = [&](int it, int slot) {
        const int tile = bid + (it >> 6) * GRID;
        const int kt = it & 63;
        const int mi = tile >> 5;              // tile / TILES_N
        const int ni = tile & (TILES_N - 1);
        const char* a = (const char*)g_xn +
            ((size_t)(mi * BM + r0c) * DIN + (size_t)kt * BK + cc * 8) * 2;
        const char* b = (const char*)g_wq +
            ((size_t)(ni * BN + r0c) * DIN + (size_t)kt * BK + cc * 8) * 2;
        const uint32_t sdst = sb + (uint32_t)slot * STAGE_B + so_base;
#pragma unroll
        for (int i = 0; i < 8; i++)
            cp_async16(sdst + i * (16 * 128), a + (size_t)i * (16 * DIN * 2));
#pragma unroll
        for (int i = 0; i < 8; i++)
            cp_async16(sdst + TILE_B + i * (16 * 128),
                       b + (size_t)i * (16 * DIN * 2));
    };

    // ---- ldmatrix base offsets (kk=0); off(kk) = off0 ^ (kk << 5)
    const int rA0 = warp_m * 64 + (lane & 15);
    const int cgA = lane >> 4;
    const int gB4 = lane >> 3;
    const int rB0 = warp_n * 64 + ((gB4 & 2) << 2) + (lane & 7);
    const int cgB = gB4 & 1;

    uint32_t offA0[4], offB0[4];
#pragma unroll
    for (int mi = 0; mi < 4; mi++) {
        const int r = rA0 + mi * 16;
        offA0[mi] = (uint32_t)(r * 128 + ((cgA ^ (r & 7)) << 4));
    }
#pragma unroll
    for (int p = 0; p < 4; p++) {
        const int r = rB0 + p * 16;
        offB0[p] = (uint32_t)(r * 128 + ((cgB ^ (r & 7)) << 4)) + TILE_B;
    }

    float acc[4][8][4];
#pragma unroll
    for (int mi = 0; mi < 4; mi++)
#pragma unroll
        for (int nj = 0; nj < 8; nj++)
#pragma unroll
            for (int e = 0; e < 4; e++) acc[mi][nj][e] = 0.f;

    uint32_t af[2][4][4], bf[2][4][4];   // [buf][frag][reg]

    auto load_frags = [&](int buf, uint32_t base, int kk) {
        const uint32_t kx = (uint32_t)(kk << 5);
#pragma unroll
        for (int mi = 0; mi < 4; mi++)
            LDSM_X4(af[buf][mi][0], af[buf][mi][1], af[buf][mi][2],
                    af[buf][mi][3], base + (offA0[mi] ^ kx));
#pragma unroll
        for (int p = 0; p < 4; p++)
            LDSM_X4(bf[buf][p][0], bf[buf][p][1], bf[buf][p][2],
                    bf[buf][p][3], base + (offB0[p] ^ kx));
    };

    auto do_mma = [&](int buf) {
#pragma unroll
        for (int mi = 0; mi < 4; mi++)
#pragma unroll
            for (int p = 0; p < 4; p++) {
                MMA16816(acc[mi][2 * p],     af[buf][mi], bf[buf][p][0], bf[buf][p][1]);
                MMA16816(acc[mi][2 * p + 1], af[buf][mi], bf[buf][p][2], bf[buf][p][3]);
            }
    };

    const int col_l = (lane & 3) * 2;

    // epilogue for a finished tile: *gamma, write f32
    auto epilogue = [&](int tile) {
        const int m0 = (tile >> 5) * BM;
        const int n0 = (tile & (TILES_N - 1)) * BN;
        const float* gptr = gamma + n0 + warp_n * 64;
        const int row_base = m0 + warp_m * 64 + (lane >> 2);
#pragma unroll
        for (int mi = 0; mi < 4; mi++) {
            float* op0 = out + (size_t)(row_base + mi * 16) * DOUT + n0 + warp_n * 64;
            float* op1 = op0 + (size_t)8 * DOUT;
#pragma unroll
            for (int nj = 0; nj < 8; nj++) {
                const float g0 = __ldg(gptr + nj * 8 + col_l);
                const float g1 = __ldg(gptr + nj * 8 + col_l + 1);
                float2 v0, v1;
                v0.x = acc[mi][nj][0] * g0;
                v0.y = acc[mi][nj][1] * g1;
                v1.x = acc[mi][nj][2] * g0;
                v1.y = acc[mi][nj][3] * g1;
                *reinterpret_cast<float2*>(op0 + nj * 8 + col_l) = v0;
                *reinterpret_cast<float2*>(op1 + nj * 8 + col_l) = v1;
                acc[mi][nj][0] = 0.f; acc[mi][nj][1] = 0.f;
                acc[mi][nj][2] = 0.f; acc[mi][nj][3] = 0.f;
            }
        }
    };

    // ---- prologue: fill flat iters 0 and 1, publish stage 0, prefetch frags
    fill(0, 0); CP_COMMIT();
    fill(1, 1); CP_COMMIT();
    asm volatile("cp.async.wait_group 1;" ::: "memory");
    __syncthreads();
    load_frags(0, sb, 0);

    // ---- persistent main loop over the flat iteration space
    int stage = 0;
    int cur_tile = bid;
    for (int it = 0; it < total; it++) {
        const uint32_t base = sb + (uint32_t)stage * STAGE_B;

        if (it + 2 < total) {
            int ns = stage + 2; if (ns >= STAGES) ns -= STAGES;
            fill(it + 2, ns);
        }
        CP_COMMIT();

#pragma unroll
        for (int kk = 0; kk < 3; kk++) {
            load_frags((kk + 1) & 1, base, kk + 1);
            do_mma(kk & 1);
        }
        do_mma(1);   // kk=3

        asm volatile("cp.async.wait_group 1;" ::: "memory");
        __syncthreads();

        stage = stage + 1; if (stage >= STAGES) stage -= STAGES;
        if (it + 1 < total)
            load_frags(0, sb + (uint32_t)stage * STAGE_B, 0);

        if ((it & 63) == 63) {       // tile finished: overlapped epilogue
            epilogue(cur_tile);
            cur_tile += GRID;
        }
    }
}

// ------------------------------- launch --------------------------------------
extern "C" void kernel_launch(void* const* d_in, const int* in_sizes, int n_in,
                              void* d_out, int out_size) {
    const float* x     = (const float*)d_in[0];  // [2,4096,4096]
    const float* nw    = (const float*)d_in[1];  // [4096]
    const float* wq    = (const float*)d_in[2];  // [4096,4096]
    const float* gamma = (const float*)d_in[3];  // [4096]
    float* out = (float*)d_out;

    cudaFuncSetAttribute(bitlinear_gemm_kernel,
                         cudaFuncAttributeMaxDynamicSharedMemorySize, SMEM_SZ);

    dummy_kernel<<<1, 32>>>();   // keeps ncu -s5 capture on the GEMM
    rmsnorm_kernel<<<MROWS, 256>>>(x, nw);
    wconv_kernel<<<4096, 256>>>(wq);
    bitlinear_gemm_kernel<<<GRID, NTHREADS, SMEM_SZ>>>(gamma, out);
}

// round 11
// speedup vs baseline: 1.2570x; 1.2570x over previous
#include <cuda_runtime.h>
#include <cuda_fp16.h>
#include <cstdint>

// ----------------------------------------------------------------------------
// BitLinear: y = RMSNorm(x) @ w_q^T * gamma
// R1: harness PTX is baseline sm_103 (no 'a') -> no tcgen05.
// R9: 64x64 warp tiles, 128-thr CTAs, occ2: tensor 89.5%, 553us total (BEST).
// R10 FAILED (713us): persistent flat loop recomputed 64-bit tile addressing
//     per iteration -> alu 17.3%, issue 39.5%, tensor 67.8%.
// R11: persistence with HOISTED addressing: per-tile bases computed once per
//     64 kts; inner fill is base + kt*128 (one LEA). Pipeline crosses tile
//     boundaries; epilogue overlaps next tile's HMMAs.
// ----------------------------------------------------------------------------

#define DIN   4096
#define DOUT  4096
#define MROWS 8192

__device__ __align__(256) __half g_xn[(size_t)MROWS * DIN];
__device__ __align__(256) __half g_wq[(size_t)DOUT * DIN];

// ---------------------------- PTX helpers -----------------------------------
__device__ __forceinline__ uint32_t smem_u32(const void* p) {
    uint32_t a;
    asm("{ .reg .u64 t; cvta.to.shared.u64 t, %1; cvt.u32.u64 %0, t; }"
        : "=r"(a) : "l"(p));
    return a;
}

__device__ __forceinline__ void cp_async16(uint32_t dst, const void* src) {
    asm volatile("cp.async.cg.shared.global [%0], [%1], 16;"
                 :: "r"(dst), "l"(src));
}

#define CP_COMMIT() asm volatile("cp.async.commit_group;" ::: "memory")

#define LDSM_X4(r0, r1, r2, r3, addr) \
    asm volatile("ldmatrix.sync.aligned.m8n8.x4.shared.b16 {%0,%1,%2,%3}, [%4];" \
                 : "=r"(r0), "=r"(r1), "=r"(r2), "=r"(r3) : "r"(addr))

#define MMA16816(d, a, b0, b1) \
    asm volatile("mma.sync.aligned.m16n8k16.row.col.f32.f16.f16.f32 " \
                 "{%0,%1,%2,%3}, {%4,%5,%6,%7}, {%8,%9}, {%0,%1,%2,%3};" \
                 : "+f"((d)[0]), "+f"((d)[1]), "+f"((d)[2]), "+f"((d)[3]) \
                 : "r"((a)[0]), "r"((a)[1]), "r"((a)[2]), "r"((a)[3]), \
                   "r"(b0), "r"(b1))

// ----------------------------- GEMM config ----------------------------------
constexpr int BM = 128, BN = 128, BK = 64;
constexpr int KTILES = DIN / BK;               // 64
constexpr int STAGES = 3;
constexpr int TILE_B  = BM * BK * 2;           // 16384 B per fp16 tile
constexpr int STAGE_B = 2 * TILE_B;            // A + B = 32768
constexpr int SMEM_SZ = STAGES * STAGE_B;      // 98304 (2 CTAs/SM)
constexpr int NTHREADS = 128;                  // 4 warps, warp tile 64x64
constexpr int GRID = 304;                      // 152 SMs x 2 CTAs (persistent)
constexpr int NTILES = (MROWS / BM) * (DOUT / BN);  // 2048
constexpr int TILES_N = DOUT / BN;             // 32

// ------------------------ Kernel 0: dummy (ncu window shift) -----------------
__global__ void dummy_kernel() {}

// ------------------------ Kernel 1: RMSNorm -> fp16 --------------------------
__global__ __launch_bounds__(256) void rmsnorm_kernel(
    const float* __restrict__ x, const float* __restrict__ nw) {
    const int row = blockIdx.x;
    const float4* xr = reinterpret_cast<const float4*>(x) + (size_t)row * (DIN / 4);
    const float4* nw4 = reinterpret_cast<const float4*>(nw);
    const int t = threadIdx.x;

    float4 v[4];
    float ss = 0.f;
#pragma unroll
    for (int i = 0; i < 4; i++) {
        v[i] = xr[t + i * 256];
        ss += v[i].x * v[i].x + v[i].y * v[i].y + v[i].z * v[i].z + v[i].w * v[i].w;
    }
#pragma unroll
    for (int o = 16; o > 0; o >>= 1) ss += __shfl_xor_sync(0xffffffffu, ss, o);

    __shared__ float wss[8];
    __shared__ float s_scale;
    if ((t & 31) == 0) wss[t >> 5] = ss;
    __syncthreads();
    if (t == 0) {
        float tot = 0.f;
#pragma unroll
        for (int i = 0; i < 8; i++) tot += wss[i];
        s_scale = rsqrtf(tot * (1.0f / DIN) + 1e-6f);
    }
    __syncthreads();
    const float sc = s_scale;

    uint2* xo = reinterpret_cast<uint2*>(g_xn + (size_t)row * DIN);
#pragma unroll
    for (int i = 0; i < 4; i++) {
        float4 w = nw4[t + i * 256];
        __half2 h01 = __floats2half2_rn(v[i].x * sc * w.x, v[i].y * sc * w.y);
        __half2 h23 = __floats2half2_rn(v[i].z * sc * w.z, v[i].w * sc * w.w);
        uint2 u;
        u.x = *reinterpret_cast<uint32_t*>(&h01);
        u.y = *reinterpret_cast<uint32_t*>(&h23);
        xo[t + i * 256] = u;
    }
}

// ------------------------ Kernel 2: w_q fp32 -> fp16 --------------------------
__global__ __launch_bounds__(256) void wconv_kernel(const float* __restrict__ w) {
    const size_t gid = (size_t)blockIdx.x * 256 + threadIdx.x;
    const float4* w4 = reinterpret_cast<const float4*>(w);
    uint2* o = reinterpret_cast<uint2*>(g_wq);
#pragma unroll
    for (int i = 0; i < 4; i++) {
        size_t idx = gid + (size_t)i * 1048576;
        float4 v = w4[idx];
        __half2 h01 = __floats2half2_rn(v.x, v.y);
        __half2 h23 = __floats2half2_rn(v.z, v.w);
        uint2 u;
        u.x = *reinterpret_cast<uint32_t*>(&h01);
        u.y = *reinterpret_cast<uint32_t*>(&h23);
        o[idx] = u;
    }
}

// ------------------------ Kernel 3: persistent HMMA GEMM ---------------------
// 128 threads = 4 warps, 2(m) x 2(n), warp tile 64x64; 2 CTAs/SM; persistent
// with per-tile hoisted addressing.
__global__ __launch_bounds__(NTHREADS, 2)
void bitlinear_gemm_kernel(const float* __restrict__ gamma, float* __restrict__ out) {
    extern __shared__ char smem[];
    const uint32_t sb = smem_u32(smem);
    const int tid = threadIdx.x;
    const int wid = tid >> 5;
    const int lane = tid & 31;
    const int warp_m = wid >> 1;       // 0..1
    const int warp_n = wid & 1;        // 0..1
    const int bid = blockIdx.x;

    // ---- per-thread copy geometry: 1024 chunks/tile, 128 thr -> 8 each
    const int cc = tid & 7;
    const int r0c = tid >> 3;          // 0..15; r&7 invariant under +16
    const uint32_t so_base = (uint32_t)(r0c * 128 + ((cc ^ (r0c & 7)) << 4));

    // per-tile base pointers (computed once per 64 kt-steps)
    auto tile_bases = [&](int t, const char*& a, const char*& b) {
        const int mi = t >> 5;                 // t / TILES_N
        const int ni = t & (TILES_N - 1);
        a = (const char*)g_xn + ((size_t)(mi * BM + r0c) * DIN + cc * 8) * 2;
        b = (const char*)g_wq + ((size_t)(ni * BN + r0c) * DIN + cc * 8) * 2;
    };

    // fill stage `slot` from tile bases (a,b) at k-chunk kt: one LEA each
    auto fill = [&](const char* a, const char* b, int kt, int slot) {
        const uint32_t sdst = sb + (uint32_t)slot * STAGE_B + so_base;
        const char* ak = a + (uint32_t)kt * 128;
        const char* bk = b + (uint32_t)kt * 128;
#pragma unroll
        for (int i = 0; i < 8; i++)
            cp_async16(sdst + i * (16 * 128), ak + (size_t)i * (16 * DIN * 2));
#pragma unroll
        for (int i = 0; i < 8; i++)
            cp_async16(sdst + TILE_B + i * (16 * 128),
                       bk + (size_t)i * (16 * DIN * 2));
    };

    // ---- ldmatrix base offsets (kk=0); off(kk) = off0 ^ (kk << 5)
    const int rA0 = warp_m * 64 + (lane & 15);
    const int cgA = lane >> 4;
    const int gB4 = lane >> 3;
    const int rB0 = warp_n * 64 + ((gB4 & 2) << 2) + (lane & 7);
    const int cgB = gB4 & 1;

    uint32_t offA0[4], offB0[4];
#pragma unroll
    for (int mi = 0; mi < 4; mi++) {
        const int r = rA0 + mi * 16;
        offA0[mi] = (uint32_t)(r * 128 + ((cgA ^ (r & 7)) << 4));
    }
#pragma unroll
    for (int p = 0; p < 4; p++) {
        const int r = rB0 + p * 16;
        offB0[p] = (uint32_t)(r * 128 + ((cgB ^ (r & 7)) << 4)) + TILE_B;
    }

    float acc[4][8][4];
#pragma unroll
    for (int mi = 0; mi < 4; mi++)
#pragma unroll
        for (int nj = 0; nj < 8; nj++)
#pragma unroll
            for (int e = 0; e < 4; e++) acc[mi][nj][e] = 0.f;

    uint32_t af[2][4][4], bf[2][4][4];   // [buf][frag][reg]

    auto load_frags = [&](int buf, uint32_t base, int kk) {
        const uint32_t kx = (uint32_t)(kk << 5);
#pragma unroll
        for (int mi = 0; mi < 4; mi++)
            LDSM_X4(af[buf][mi][0], af[buf][mi][1], af[buf][mi][2],
                    af[buf][mi][3], base + (offA0[mi] ^ kx));
#pragma unroll
        for (int p = 0; p < 4; p++)
            LDSM_X4(bf[buf][p][0], bf[buf][p][1], bf[buf][p][2],
                    bf[buf][p][3], base + (offB0[p] ^ kx));
    };

    auto do_mma = [&](int buf) {
#pragma unroll
        for (int mi = 0; mi < 4; mi++)
#pragma unroll
            for (int p = 0; p < 4; p++) {
                MMA16816(acc[mi][2 * p],     af[buf][mi], bf[buf][p][0], bf[buf][p][1]);
                MMA16816(acc[mi][2 * p + 1], af[buf][mi], bf[buf][p][2], bf[buf][p][3]);
            }
    };

    const int col_l = (lane & 3) * 2;

    // epilogue: *gamma, write f32, zero accumulators
    auto epilogue = [&](int t) {
        const int m0 = (t >> 5) * BM;
        const int n0 = (t & (TILES_N - 1)) * BN;
        const float* gptr = gamma + n0 + warp_n * 64;
        const int row_base = m0 + warp_m * 64 + (lane >> 2);
#pragma unroll
        for (int mi = 0; mi < 4; mi++) {
            float* op0 = out + (size_t)(row_base + mi * 16) * DOUT + n0 + warp_n * 64;
            float* op1 = op0 + (size_t)8 * DOUT;
#pragma unroll
            for (int nj = 0; nj < 8; nj++) {
                const float g0 = __ldg(gptr + nj * 8 + col_l);
                const float g1 = __ldg(gptr + nj * 8 + col_l + 1);
                float2 v0, v1;
                v0.x = acc[mi][nj][0] * g0;
                v0.y = acc[mi][nj][1] * g1;
                v1.x = acc[mi][nj][2] * g0;
                v1.y = acc[mi][nj][3] * g1;
                *reinterpret_cast<float2*>(op0 + nj * 8 + col_l) = v0;
                *reinterpret_cast<float2*>(op1 + nj * 8 + col_l) = v1;
                acc[mi][nj][0] = 0.f; acc[mi][nj][1] = 0.f;
                acc[mi][nj][2] = 0.f; acc[mi][nj][3] = 0.f;
            }
        }
    };

    // ---- prologue: first tile's kt0/kt1, publish stage 0, prefetch frags
    const char *aT, *bT, *aN, *bN;
    tile_bases(bid, aT, bT);
    fill(aT, bT, 0, 0); CP_COMMIT();
    fill(aT, bT, 1, 1); CP_COMMIT();
    asm volatile("cp.async.wait_group 1;" ::: "memory");
    __syncthreads();
    load_frags(0, sb, 0);

    // ---- persistent tile loop; pipeline never drains across boundaries
    int stage = 0;
    for (int t = bid; t < NTILES; t += GRID) {
        const int tn = t + GRID;
        if (tn < NTILES) tile_bases(tn, aN, bN);
        else { aN = aT; bN = bT; }          // harmless refetch on last tile

        for (int kt = 0; kt < KTILES; kt++) {
            const uint32_t base = sb + (uint32_t)stage * STAGE_B;

            const int fk = kt + 2;
            int ns = stage + 2; if (ns >= STAGES) ns -= STAGES;
            if (fk < KTILES) fill(aT, bT, fk, ns);
            else             fill(aN, bN, fk - KTILES, ns);
            CP_COMMIT();

#pragma unroll
            for (int kk = 0; kk < 3; kk++) {
                load_frags((kk + 1) & 1, base, kk + 1);
                do_mma(kk & 1);
            }
            do_mma(1);   // kk=3

            asm volatile("cp.async.wait_group 1;" ::: "memory");
            __syncthreads();

            stage = stage + 1; if (stage >= STAGES) stage -= STAGES;
            load_frags(0, sb + (uint32_t)stage * STAGE_B, 0);
        }

        epilogue(t);                         // overlaps next tile's HMMAs
        aT = aN; bT = bN;
    }
}

// ------------------------------- launch --------------------------------------
extern "C" void kernel_launch(void* const* d_in, const int* in_sizes, int n_in,
                              void* d_out, int out_size) {
    const float* x     = (const float*)d_in[0];  // [2,4096,4096]
    const float* nw    = (const float*)d_in[1];  // [4096]
    const float* wq    = (const float*)d_in[2];  // [4096,4096]
    const float* gamma = (const float*)d_in[3];  // [4096]
    float* out = (float*)d_out;

    cudaFuncSetAttribute(bitlinear_gemm_kernel,
                         cudaFuncAttributeMaxDynamicSharedMemorySize, SMEM_SZ);

    dummy_kernel<<<1, 32>>>();   // keeps ncu -s5 capture on the GEMM
    rmsnorm_kernel<<<MROWS, 256>>>(x, nw);
    wconv_kernel<<<4096, 256>>>(wq);
    bitlinear_gemm_kernel<<<GRID, NTHREADS, SMEM_SZ>>>(gamma, out);
}